// round 17
// baseline (speedup 1.0000x reference)
#include <cuda_runtime.h>

// SparseSphereConv: BS=4, C_IN=C_OUT=32, V=40962, K=9
// out[b,o,v] = mask[b,v] * ( bias[o] + sum_{c,k} (sum_{k'} x[b,c,idx[v,k']] * itp[v,k',k]) * w[o,c,k] )
// mask[b,v] = any_{c,k'} ( x[b,c,idx[v,k']] != 0 )
//
// R17: (1) cross-iteration gather pipelining — group g+1's gathers issue
// right after barrier B and their ~600-cyc L2 latency hides behind
// stage2+stage3; consumed by next iteration's interp. (2) wprep folded into
// the transpose kernel (-5us launch overhead). Everything else as R16.

#define V_TOT 40962
#define NBS   4
#define NCI   32
#define NCO   32
#define KNB   9
#define NROWS 128   // NBS * NCI
#define VB    4     // vertices per group
#define NGRP  10241 // ceil(V_TOT / VB)
#define SRED_P 34   // s_red inner pad: conflict-free r/w

typedef unsigned long long ull;

// x transposed to [V][128], row r = b*32 + c  (21 MB, L2-resident)
static __device__ float g_xt[(size_t)V_TOT * NROWS];
// packed conv weights: g_w2[((cg*4+kp)*4+ci)*32+o] = (w[o][cg*4+ci][2kp], w[..][2kp+1])
static __device__ ull g_w2[8 * 4 * 4 * 32];
// packed k=8 tail:    g_w8[(cg*2+pr)*32+o] = (w8[ci=2pr], w8[ci=2pr+1])
static __device__ ull g_w8[8 * 2 * 32];

// ---------------- packed fp32 helpers (sm_103a f32x2 pipe) ----------------
__device__ __forceinline__ ull ffma2(ull a, ull b, ull c) {
    ull d; asm("fma.rn.f32x2 %0, %1, %2, %3;" : "=l"(d) : "l"(a), "l"(b), "l"(c)); return d;
}
__device__ __forceinline__ ull fadd2(ull a, ull b) {
    ull d; asm("add.rn.f32x2 %0, %1, %2;" : "=l"(d) : "l"(a), "l"(b)); return d;
}
__device__ __forceinline__ ull pack2(float lo, float hi) {
    ull d; asm("mov.b64 %0, {%1, %2};" : "=l"(d) : "f"(lo), "f"(hi)); return d;
}
__device__ __forceinline__ float2 unpack2(ull v) {
    float2 r; asm("mov.b64 {%0, %1}, %2;" : "=f"(r.x), "=f"(r.y) : "l"(v)); return r;
}

// ---------------------------------------------------------------------------
// Kernel 1: transpose x [128 rows (b*32+c), V] -> xt [V][128]
// Blocks (bx<16, by==0) additionally pack the conv weights (wprep fold).
// ---------------------------------------------------------------------------
__global__ void transpose_kernel(const float* __restrict__ x,
                                 const float* __restrict__ conv_w) {
    __shared__ float sh[32][33];
    const int n0 = blockIdx.x * 32;
    const int r0 = blockIdx.y * 32;
    const int tx = threadIdx.x, ty = threadIdx.y;
#pragma unroll
    for (int i = 0; i < 4; i++) {
        const int n = n0 + tx;
        const int r = r0 + ty + 8 * i;
        sh[ty + 8 * i][tx] = (n < V_TOT) ? x[(size_t)r * V_TOT + n] : 0.0f;
    }
    __syncthreads();
#pragma unroll
    for (int i = 0; i < 4; i++) {
        const int n = n0 + ty + 8 * i;
        if (n < V_TOT) g_xt[(size_t)n * NROWS + r0 + tx] = sh[tx][ty + 8 * i];
    }

    // ---- weight packing (16 blocks x 256 threads = 4096 = |g_w2|) ----
    if (blockIdx.y == 0 && blockIdx.x < 16) {
        const int t = blockIdx.x * 256 + (ty * 32 + tx);
        {
            const int o  = t & 31;
            int r = t >> 5;
            const int ci = r & 3;  r >>= 2;
            const int kp = r & 3;  r >>= 2;
            const int cg = r;
            const float* wt = conv_w + ((size_t)o * NCI + (cg * 4 + ci)) * KNB;
            g_w2[t] = pack2(wt[2 * kp], wt[2 * kp + 1]);
        }
        if (t < 8 * 2 * 32) {
            const int o  = t & 31;
            const int pr = (t >> 5) & 1;
            const int cg = t >> 6;
            const float a = conv_w[((size_t)o * NCI + (cg * 4 + 2 * pr)) * KNB + 8];
            const float b = conv_w[((size_t)o * NCI + (cg * 4 + 2 * pr + 1)) * KNB + 8];
            g_w8[t] = pack2(a, b);
        }
    }
}

// ---------------------------------------------------------------------------
// Kernel 2: fused gather + interp + conv + mask. 3 CTAs/SM, gather pipelined.
// ---------------------------------------------------------------------------
__global__ __launch_bounds__(256, 3)
void sphere_kernel(const int*   __restrict__ nbr,
                   const float* __restrict__ itp,
                   const float* __restrict__ conv_b,
                   float*       __restrict__ out)
{
    __shared__ __align__(16) float4 s_fA[VB][NBS][NCI];     // interp k0..3
    __shared__ __align__(16) float4 s_fB[VB][NBS][NCI];     // interp k4..7
    __shared__ __align__(16) float  s_f8[VB][NBS][NCI];     // interp k8
    __shared__ float                s_red[8][VB][NBS][SRED_P]; // [cg][v][b][o]
    __shared__ __align__(16) float  s_itp[2][VB][KNB][12];  // double-buffered metadata
    __shared__ int                  s_idx[2][VB][KNB];
    __shared__ int                  s_nz[2][VB][NBS];

    const int t    = threadIdx.x;
    const int lane = t & 31;
    const int wid  = t >> 5;

    // --- conv identity: warp = c-group, lane = output channel ---
    const int o  = lane;
    const int cg = wid;
    const ull* wbase2 = g_w2 + (size_t)cg * (4 * 4 * 32) + o;
    const ull* wbase8 = g_w8 + (size_t)cg * (2 * 32) + o;

    // --- stage-3 identity: e = t (+256): b=e>>7, oo=(e>>2)&31, vloc=e&3 ---
    const int oo3 = (t >> 2) & 31;
    const int vl3 = t & 3;
    const int b3  = t >> 7;
    const float bias3 = conv_b[oo3];

    // --- stage-1 identity: warp -> (vertex, b-pair half); lane -> (b, c-pair) ---
    const int vI   = wid >> 1;                 // vertex 0..3
    const int half = wid & 1;                  // b-pair: {0,1} or {2,3}
    const int bW   = 2 * half + (lane >> 4);   // this thread's b
    const int c0   = 2 * (lane & 15);          // rows (bW,c0) and (bW,c0+1)
    const int rowbase = bW * 32 + c0;          // even -> 8B-aligned gather

    const float2* xb = (const float2*)(g_xt + rowbase);

    const int g0 = blockIdx.x;
    int p = 0;

    // ---- prime: metadata for first group into buffer 0 ----
    if (g0 < NGRP) {
        const int v0p = g0 * VB;
        if (t < VB * KNB) {
            const int vl = t / KNB, k = t - KNB * vl;
            const int vg = v0p + vl;
            s_idx[0][vl][k] = (vg < V_TOT) ? nbr[(size_t)vg * KNB + k] : 0;
        }
#pragma unroll
        for (int e = t; e < VB * KNB * KNB; e += 256) {
            const int vl  = e / 81;
            const int rem = e - 81 * vl;
            const int vg  = v0p + vl;
            s_itp[0][vl][rem / KNB][rem % KNB] =
                (vg < V_TOT) ? itp[(size_t)vg * 81 + rem] : 0.0f;
        }
    }
    __syncthreads();

    // ---- prime: gather for the first group ----
    float2 gv[KNB];
    if (g0 < NGRP) {
#pragma unroll
        for (int k = 0; k < KNB; k++)
            gv[k] = __ldg(xb + (size_t)s_idx[0][vI][k] * (NROWS / 2));
    }

    for (int g = g0; g < NGRP; g += gridDim.x) {
        const int v0 = g * VB;

        // ---- stage 1: mask + interp (gv already in flight / arrived) ----
        bool nz = false;
#pragma unroll
        for (int k = 0; k < KNB; k++) nz |= (gv[k].x != 0.0f) | (gv[k].y != 0.0f);
        const unsigned bm = __ballot_sync(0xFFFFFFFFu, nz);
        if (lane == 0) {
            s_nz[p][vI][2 * half]     = (bm & 0xFFFFu) ? 1 : 0;
            s_nz[p][vI][2 * half + 1] = (bm >> 16)     ? 1 : 0;
        }

        {
            ull xA01 = 0, xA23 = 0, xA45 = 0, xA67 = 0; float xA8 = 0.0f;
            ull yA01 = 0, yA23 = 0, yA45 = 0, yA67 = 0; float yA8 = 0.0f;
#pragma unroll
            for (int k = 0; k < KNB; k++) {
                const ulonglong2 ia = *(const ulonglong2*)&s_itp[p][vI][k][0];
                const ulonglong2 ib = *(const ulonglong2*)&s_itp[p][vI][k][4];
                const float      i8 = s_itp[p][vI][k][8];
                const float gx = gv[k].x, gy = gv[k].y;
                const ull g2x = pack2(gx, gx);
                const ull g2y = pack2(gy, gy);
                xA01 = ffma2(g2x, ia.x, xA01);
                xA23 = ffma2(g2x, ia.y, xA23);
                xA45 = ffma2(g2x, ib.x, xA45);
                xA67 = ffma2(g2x, ib.y, xA67);
                xA8  = fmaf(gx, i8, xA8);
                yA01 = ffma2(g2y, ia.x, yA01);
                yA23 = ffma2(g2y, ia.y, yA23);
                yA45 = ffma2(g2y, ib.x, yA45);
                yA67 = ffma2(g2y, ib.y, yA67);
                yA8  = fmaf(gy, i8, yA8);
            }
            ulonglong2 w;
            w.x = xA01; w.y = xA23; *(ulonglong2*)&s_fA[vI][bW][c0]     = w;
            w.x = yA01; w.y = yA23; *(ulonglong2*)&s_fA[vI][bW][c0 + 1] = w;
            w.x = xA45; w.y = xA67; *(ulonglong2*)&s_fB[vI][bW][c0]     = w;
            w.x = yA45; w.y = yA67; *(ulonglong2*)&s_fB[vI][bW][c0 + 1] = w;
            *(float2*)&s_f8[vI][bW][c0] = make_float2(xA8, yA8);
        }

        // ---- prefetch metadata for next group into buf p^1 ----
        const int gn = g + gridDim.x;
        const int pn = p ^ 1;
        if (gn < NGRP) {
            const int v0n = gn * VB;
            if (t < VB * KNB) {
                const int vl = t / KNB, k = t - KNB * vl;
                const int vg = v0n + vl;
                s_idx[pn][vl][k] = (vg < V_TOT) ? nbr[(size_t)vg * KNB + k] : 0;
            }
#pragma unroll
            for (int e = t; e < VB * KNB * KNB; e += 256) {
                const int vl  = e / 81;
                const int rem = e - 81 * vl;
                const int vg  = v0n + vl;
                s_itp[pn][vl][rem / KNB][rem % KNB] =
                    (vg < V_TOT) ? itp[(size_t)vg * 81 + rem] : 0.0f;
            }
        }
        __syncthreads();  // B: s_f + next meta ready; orders prev stage-3 reads

        // ---- pipelined gather for group g+1: latency hides behind stage 2/3 ----
        if (gn < NGRP) {
#pragma unroll
            for (int k = 0; k < KNB; k++)
                gv[k] = __ldg(xb + (size_t)s_idx[pn][vI][k] * (NROWS / 2));
        }

        // ---- stage 2: conv. Weights reloaded each group (L1-hit) ----
        ull Wk2[4][4];
        ull W8p[2];
#pragma unroll
        for (int kp = 0; kp < 4; kp++)
#pragma unroll
            for (int ci = 0; ci < 4; ci++)
                Wk2[ci][kp] = wbase2[(kp * 4 + ci) * 32];
        W8p[0] = wbase8[0];
        W8p[1] = wbase8[32];

#pragma unroll
        for (int v = 0; v < VB; v++) {
#pragma unroll
            for (int b = 0; b < NBS; b++) {
                const ulonglong2* pA = (const ulonglong2*)&s_fA[v][b][cg * 4];
                const ulonglong2* pB = (const ulonglong2*)&s_fB[v][b][cg * 4];
                ull a0 = 0, a1 = 0, a2 = 0, a3 = 0, a8 = 0;
#pragma unroll
                for (int ci = 0; ci < 4; ci++) {
                    const ulonglong2 fa = pA[ci];
                    const ulonglong2 fb = pB[ci];
                    a0 = ffma2(fa.x, Wk2[ci][0], a0);
                    a1 = ffma2(fa.y, Wk2[ci][1], a1);
                    a2 = ffma2(fb.x, Wk2[ci][2], a2);
                    a3 = ffma2(fb.y, Wk2[ci][3], a3);
                }
                const ulonglong2 f8p = *(const ulonglong2*)&s_f8[v][b][cg * 4];
                a8 = ffma2(f8p.x, W8p[0], a8);
                a8 = ffma2(f8p.y, W8p[1], a8);

                ull sp = fadd2(fadd2(a0, a1), fadd2(a2, a3));
                sp = fadd2(sp, a8);
                const float2 sf = unpack2(sp);
                s_red[cg][v][b][o] = sf.x + sf.y;
            }
        }
        __syncthreads();  // C: s_red ready (also protects next-iter s_f STS)

        // ---- stage 3: reduce 8 cgroups, bias, mask, coalesced store ----
#pragma unroll
        for (int r = 0; r < 2; r++) {
            const int b = b3 + r * 2;
            float s = 0.0f;
#pragma unroll
            for (int w8 = 0; w8 < 8; w8++)
                s += s_red[w8][vl3][b][oo3];
            s = (s + bias3) * (float)s_nz[p][vl3][b];
            const int vg = v0 + vl3;
            if (vg < V_TOT)
                out[((size_t)b * NCO + oo3) * V_TOT + vg] = s;
        }

        p ^= 1;
    }
}

extern "C" void kernel_launch(void* const* d_in, const int* in_sizes, int n_in,
                              void* d_out, int out_size) {
    (void)in_sizes; (void)n_in; (void)out_size;
    const float* x      = (const float*)d_in[0];
    const int*   nbr    = (const int*)  d_in[1];
    const float* itp    = (const float*)d_in[2];
    const float* conv_w = (const float*)d_in[3];
    const float* conv_b = (const float*)d_in[4];
    float*       out    = (float*)d_out;

    dim3 tb(32, 8);
    dim3 tg((V_TOT + 31) / 32, NROWS / 32);
    transpose_kernel<<<tg, tb>>>(x, conv_w);   // also packs weights (bx<16, by==0)

    // 444 = 3 CTAs x 148 SMs: fully-resident persistent grid
    sphere_kernel<<<444, 256>>>(nbr, itp, conv_b, out);
}